// round 14
// baseline (speedup 1.0000x reference)
#include <cuda_runtime.h>
#include <math.h>

#define B_N   8
#define T_LEN 48000
#define MAX_H 60
#define C_N   100
#define NFORM 5

#define L1_N   3000
#define L1_PAD 3008
#define L2_N   188
#define L2_PAD 192
#define L3_N   12

__device__ float g_inner0[B_N][T_LEN];
__device__ float g_S1[B_N * L1_N];

#define TWOPI_F   6.28318548202514648f
#define C2_ABS    1.7484556e-7f
#define INV2PI_F  0.15915494309189535f
#define RMAGIC    12582912.0f        /* 1.5*2^23 RN-ties-even rounder */

#define OSC_T     128
#define AROW_PAD  62

#define SC1   9.765625e-04f          /* 2^-10 */
#define SC2   9.5367431640625e-07f   /* 2^-20 */

typedef unsigned long long u64;
__device__ __forceinline__ u64 pk2(float lo, float hi) {
    u64 r; asm("mov.b64 %0, {%1, %2};" : "=l"(r) : "f"(lo), "f"(hi)); return r;
}
__device__ __forceinline__ void unpk2(u64 v, float& lo, float& hi) {
    asm("mov.b64 {%0, %1}, %2;" : "=f"(lo), "=f"(hi) : "l"(v));
}
__device__ __forceinline__ u64 add2(u64 a, u64 b) {
    u64 r; asm("add.rn.f32x2 %0, %1, %2;" : "=l"(r) : "l"(a), "l"(b)); return r;
}
__device__ __forceinline__ u64 mul2(u64 a, u64 b) {
    u64 r; asm("mul.rn.f32x2 %0, %1, %2;" : "=l"(r) : "l"(a), "l"(b)); return r;
}
__device__ __forceinline__ u64 fma2(u64 a, u64 b, u64 c) {
    u64 r; asm("fma.rn.f32x2 %0, %1, %2, %3;" : "=l"(r) : "l"(a), "l"(b), "l"(c)); return r;
}

// ---------------------------------------------------------------------------
// FUSED scan kernel: one CTA per batch, 1024 threads.
// Level 0 (3000 16-tiles, 3/thread) -> smem tile sums -> L1/L2/L3 -> S1.
// All f32 adds identical to the previous two-kernel version (bit-exact rw16).
// ---------------------------------------------------------------------------
__global__ void __launch_bounds__(1024)
scan_fused_kernel(const float* __restrict__ f0,
                  const float* __restrict__ initial_phase,
                  float* __restrict__ out /* final_phase at tail */)
{
    int b   = blockIdx.x;
    int tid = threadIdx.x;
    __shared__ float sT1[L1_PAD];
    __shared__ float sT2[L2_PAD];
    __shared__ float sT3[L3_N];
    __shared__ float sS2[L2_N];

    const float INV_SR = 1.0f / 24000.0f;
    const float* f0b = f0 + b * T_LEN;

    // Level 0: per-16-tile sequential inclusive scan.
    for (int j = tid; j < L1_N; j += 1024) {
        const float4* src = reinterpret_cast<const float4*>(f0b + j * 16);
        float4* dst = reinterpret_cast<float4*>(&g_inner0[b][j * 16]);
        float4 v0 = src[0], v1 = src[1], v2 = src[2], v3 = src[3];
        float in[16] = {v0.x, v0.y, v0.z, v0.w, v1.x, v1.y, v1.z, v1.w,
                        v2.x, v2.y, v2.z, v2.w, v3.x, v3.y, v3.z, v3.w};
        float o[16];
        float acc = 0.0f;
        #pragma unroll
        for (int k = 0; k < 16; k++) {
            float x = __fmul_rn(__fmul_rn(TWOPI_F, in[k]), INV_SR);
            acc = __fadd_rn(acc, x);
            o[k] = acc;
        }
        dst[0] = make_float4(o[0],  o[1],  o[2],  o[3]);
        dst[1] = make_float4(o[4],  o[5],  o[6],  o[7]);
        dst[2] = make_float4(o[8],  o[9],  o[10], o[11]);
        dst[3] = make_float4(o[12], o[13], o[14], o[15]);
        sT1[j] = acc;
    }
    if (tid >= L1_N && tid < L1_PAD) sT1[tid] = 0.0f;   // covers 3000..3007
    __syncthreads();

    // L1: 188 tiles of 16, sequential fold, in-place inner1.
    if (tid < L2_N) {
        float acc = 0.0f;
        int base = tid * 16;
        #pragma unroll
        for (int k = 0; k < 16; k++) {
            acc = __fadd_rn(acc, sT1[base + k]);
            sT1[base + k] = acc;
        }
        sT2[tid] = acc;
    }
    if (tid >= L2_N && tid < L2_PAD) sT2[tid] = 0.0f;
    __syncthreads();

    // L2: 12 tiles of 16.
    if (tid < L3_N) {
        float acc = 0.0f;
        int base = tid * 16;
        #pragma unroll
        for (int k = 0; k < 16; k++) {
            acc = __fadd_rn(acc, sT2[base + k]);
            sT2[base + k] = acc;
        }
        sT3[tid] = acc;
    }
    __syncthreads();

    // L3: naive sequential scan of 12.
    if (tid == 0) {
        float acc = 0.0f;
        #pragma unroll
        for (int i = 0; i < L3_N; i++) {
            acc = __fadd_rn(acc, sT3[i]);
            sT3[i] = acc;
        }
    }
    __syncthreads();

    // S2 = inner2 + exclusive(S3)
    if (tid < L2_N) {
        int j3 = tid >> 4;
        sS2[tid] = j3 ? __fadd_rn(sT2[tid], sT3[j3 - 1]) : sT2[tid];
    }
    __syncthreads();

    // S1 = inner1 + exclusive(S2) -> global
    for (int j = tid; j < L1_N; j += 1024) {
        int j2 = j >> 4;
        g_S1[b * L1_N + j] = j2 ? __fadd_rn(sT1[j], sS2[j2 - 1]) : sT1[j];
    }

    // final_phase = fl(fl(fl(inner0[T-1] + S1[2998]) + ip)) % 2pi
    if (tid == 0) {
        float s1v = __fadd_rn(sT1[2998], sS2[186]);
        float s0  = __fadd_rn(g_inner0[b][T_LEN - 1], s1v);
        float ph  = __fadd_rn(s0, initial_phase[b]);
        out[B_N * T_LEN + b] = fmodf(ph, TWOPI_F);
    }
}

// ---------------------------------------------------------------------------
// Kernel C: oscillator (R13 form, unchanged arithmetic).
// ---------------------------------------------------------------------------
__global__ void __launch_bounds__(OSC_T)
osc_kernel(const float* __restrict__ f0,
           const float* __restrict__ amplitudes,
           const float* __restrict__ formant_freqs,
           const float* __restrict__ formant_bws,
           const float* __restrict__ formant_amps,
           const float* __restrict__ initial_phase,
           float* __restrict__ out)
{
    __shared__ float s_amp[OSC_T * AROW_PAD];

    int tid = threadIdx.x;
    int base_idx = blockIdx.x * OSC_T;

    // Cooperative coalesced load of the CTA's 128x60 amplitude tile.
    {
        const float4* gsrc =
            reinterpret_cast<const float4*>(amplitudes + (size_t)base_idx * MAX_H);
        #pragma unroll
        for (int k = 0; k < 15; k++) {
            int n = k * OSC_T + tid;
            float4 v = gsrc[n];
            int r  = n / 15;
            int c4 = n - r * 15;
            float* d = &s_amp[r * AROW_PAD + c4 * 4];
            d[0] = v.x; d[1] = v.y; d[2] = v.z; d[3] = v.w;
        }
    }
    __syncthreads();

    int idx = base_idx + tid;
    int b = idx / T_LEN;
    int t = idx - b * T_LEN;

    float f0v = f0[idx];

    // Exact harmonic count, then zero own amplitude row tail.
    int nh = min(MAX_H, (int)__fdividef(12000.0f, f0v));
    while (nh > 0 && !(__fmul_rn(f0v, (float)nh) < 12000.0f)) nh--;
    while (nh < MAX_H && __fmul_rn(f0v, (float)(nh + 1)) < 12000.0f) nh++;
    {
        float* row = &s_amp[tid * AROW_PAD];
        for (int k = nh; k < MAX_H; k++) row[k] = 0.0f;
    }

    // Compose phase: fl( fl(inner0[t] + S1[t/16 - 1]) + ip )
    int jt = t >> 4;
    float s0 = g_inner0[b][t];
    if (jt) s0 = __fadd_rn(s0, g_S1[b * L1_N + jt - 1]);
    float phase = __fadd_rn(s0, initial_phase[b]);

    // Linear interp of formant params (align_corners=True), exact f32 replica.
    const float SRC_SCALE = (float)(99.0 / 47999.0);
    float src = __fmul_rn((float)t, SRC_SCALE);
    int i0 = (int)floorf(src);
    i0 = max(0, min(C_N - 2, i0));
    float frac = __fsub_rn(src, (float)i0);
    float w0   = __fsub_rn(1.0f, frac);

    const float* fq = formant_freqs + (b * C_N + i0) * NFORM;
    const float* fb = formant_bws   + (b * C_N + i0) * NFORM;
    const float* fa = formant_amps  + (b * C_N + i0) * NFORM;

    u64 nfreq2[NFORM], bw22[NFORM], num2[NFORM];
    #pragma unroll
    for (int f = 0; f < NFORM; f++) {
        float fr = __fadd_rn(__fmul_rn(fq[f], w0), __fmul_rn(fq[f + NFORM], frac));
        float bw = __fadd_rn(__fmul_rn(fb[f], w0), __fmul_rn(fb[f + NFORM], frac));
        float am = __fadd_rn(__fmul_rn(fa[f], w0), __fmul_rn(fa[f + NFORM], frac));
        float bw2 = __fmul_rn(bw, bw);
        float num = __fmul_rn(__fmul_rn(am, bw), bw);
        float nfs = -__fmul_rn(fr,  SC1);
        float b2s = __fmul_rn(bw2, SC2);
        float nms = __fmul_rn(num, SC2);
        nfreq2[f] = pk2(nfs, nfs);
        bw22[f]   = pk2(b2s, b2s);
        num2[f]   = pk2(nms, nms);
    }
    const u64 ONE2 = pk2(1.0f, 1.0f);
    float f0s = __fmul_rn(f0v, SC1);     // exact 2^-10 scale

    const u64* arow2 = reinterpret_cast<const u64*>(&s_amp[tid * AROW_PAD]);

    u64 acc2 = pk2(0.0f, 0.0f);

    #pragma unroll
    for (int pi = 0; pi < MAX_H / 2; pi++) {
        const float hf0c = (float)(2 * pi + 1);
        const float hf1c = (float)(2 * pi + 2);

        float hfs0 = __fmul_rn(f0s, hf0c);
        float hfs1 = __fmul_rn(f0s, hf1c);
        u64 hfs2 = pk2(hfs0, hfs1);

        u64 Np2 = arow2[pi], Dp2 = ONE2;
        #pragma unroll
        for (int f = 0; f < NFORM; f++) {
            u64 d2   = add2(hfs2, nfreq2[f]);
            u64 den2 = fma2(d2, d2, bw22[f]);
            u64 nd2  = add2(den2, num2[f]);
            Np2 = mul2(Np2, nd2);
            Dp2 = mul2(Dp2, den2);
        }

        float arg0 = __fmul_rn(phase, hf0c);
        float arg1 = __fmul_rn(phase, hf1c);
        float km0  = __fmaf_rn(arg0, INV2PI_F, RMAGIC);
        float km1  = __fmaf_rn(arg1, INV2PI_F, RMAGIC);
        float kq0  = __fadd_rn(km0, -RMAGIC);
        float kq1  = __fadd_rn(km1, -RMAGIC);
        float r0   = __fmaf_rn(kq0, -TWOPI_F, arg0);
        float r1   = __fmaf_rn(kq1, -TWOPI_F, arg1);
        r0 = __fmaf_rn(kq0, C2_ABS, r0);
        r1 = __fmaf_rn(kq1, C2_ABS, r1);
        float sv0 = __sinf(r0);
        float sv1 = __sinf(r1);

        float Dp0, Dp1;
        unpk2(Dp2, Dp0, Dp1);
        float inv = __fdividef(1.0f, __fmul_rn(Dp0, Dp1));
        u64 fact2 = mul2(mul2(Np2, pk2(Dp1, Dp0)), pk2(inv, inv));

        acc2 = fma2(pk2(sv0, sv1), fact2, acc2);
    }

    float accLo, accHi;
    unpk2(acc2, accLo, accHi);
    float acc = __fadd_rn(accLo, accHi);

    float voiced = (f0v > 0.0f) ? 1.0f : 0.0f;
    out[idx] = __fmul_rn(acc, voiced);
}

// ---------------------------------------------------------------------------
extern "C" void kernel_launch(void* const* d_in, const int* in_sizes, int n_in,
                              void* d_out, int out_size)
{
    const float* f0   = (const float*)d_in[0];
    const float* amps = (const float*)d_in[1];
    const float* ffq  = (const float*)d_in[2];
    const float* fbw  = (const float*)d_in[3];
    const float* fam  = (const float*)d_in[4];
    const float* ip   = (const float*)d_in[5];
    float* out = (float*)d_out;

    scan_fused_kernel<<<B_N, 1024>>>(f0, ip, out);

    int total = B_N * T_LEN;
    osc_kernel<<<total / OSC_T, OSC_T>>>(f0, amps, ffq, fbw, fam, ip, out);
}

// round 15
// speedup vs baseline: 1.1014x; 1.1014x over previous
#include <cuda_runtime.h>
#include <math.h>

#define B_N   8
#define T_LEN 48000
#define MAX_H 60
#define C_N   100
#define NFORM 5

#define L1_N   3000
#define L1_PAD 3008
#define L2_N   188
#define L2_PAD 192
#define L3_N   12

__device__ float g_inner0[B_N][T_LEN];
__device__ float g_T1[B_N * L1_N];
__device__ float g_S1[B_N * L1_N];

#define TWOPI_F   6.28318548202514648f
#define C2_ABS    1.7484556e-7f
#define INV2PI_F  0.15915494309189535f
#define RMAGIC    12582912.0f        /* 1.5*2^23 RN-ties-even rounder */

#define SC1   9.765625e-04f          /* 2^-10 */
#define SC2   9.5367431640625e-07f   /* 2^-20 */

typedef unsigned long long u64;
__device__ __forceinline__ u64 pk2(float lo, float hi) {
    u64 r; asm("mov.b64 %0, {%1, %2};" : "=l"(r) : "f"(lo), "f"(hi)); return r;
}
__device__ __forceinline__ void unpk2(u64 v, float& lo, float& hi) {
    asm("mov.b64 {%0, %1}, %2;" : "=f"(lo), "=f"(hi) : "l"(v));
}
__device__ __forceinline__ u64 add2(u64 a, u64 b) {
    u64 r; asm("add.rn.f32x2 %0, %1, %2;" : "=l"(r) : "l"(a), "l"(b)); return r;
}
__device__ __forceinline__ u64 mul2(u64 a, u64 b) {
    u64 r; asm("mul.rn.f32x2 %0, %1, %2;" : "=l"(r) : "l"(a), "l"(b)); return r;
}
__device__ __forceinline__ u64 fma2(u64 a, u64 b, u64 c) {
    u64 r; asm("fma.rn.f32x2 %0, %1, %2, %3;" : "=l"(r) : "l"(a), "l"(b), "l"(c)); return r;
}

// ---------------------------------------------------------------------------
// Kernel A: level-0 tiles (bit-exact rw16 inner scans).
// ---------------------------------------------------------------------------
__global__ void __launch_bounds__(128)
scan_tiles_kernel(const float* __restrict__ f0)
{
    int gid = blockIdx.x * blockDim.x + threadIdx.x;
    if (gid >= B_N * L1_N) return;
    int b = gid / L1_N;
    int j = gid - b * L1_N;
    const float INV_SR = 1.0f / 24000.0f;

    const float4* src = reinterpret_cast<const float4*>(f0 + b * T_LEN + j * 16);
    float4* dst = reinterpret_cast<float4*>(&g_inner0[b][j * 16]);

    float4 v0 = src[0], v1 = src[1], v2 = src[2], v3 = src[3];
    float in[16] = {v0.x, v0.y, v0.z, v0.w, v1.x, v1.y, v1.z, v1.w,
                    v2.x, v2.y, v2.z, v2.w, v3.x, v3.y, v3.z, v3.w};
    float o[16];
    float acc = 0.0f;
    #pragma unroll
    for (int k = 0; k < 16; k++) {
        float x = __fmul_rn(__fmul_rn(TWOPI_F, in[k]), INV_SR);
        acc = __fadd_rn(acc, x);
        o[k] = acc;
    }
    dst[0] = make_float4(o[0],  o[1],  o[2],  o[3]);
    dst[1] = make_float4(o[4],  o[5],  o[6],  o[7]);
    dst[2] = make_float4(o[8],  o[9],  o[10], o[11]);
    dst[3] = make_float4(o[12], o[13], o[14], o[15]);
    g_T1[gid] = acc;
}

// ---------------------------------------------------------------------------
// Kernel B: per-batch upper levels + S1 compose + final_phase.
// ---------------------------------------------------------------------------
__global__ void __launch_bounds__(256)
scan_upper_kernel(const float* __restrict__ initial_phase,
                  float* __restrict__ out)
{
    int b   = blockIdx.x;
    int tid = threadIdx.x;
    __shared__ float sT1[L1_PAD];
    __shared__ float sT2[L2_PAD];
    __shared__ float sT3[L3_N];
    __shared__ float sS2[L2_N];

    for (int j = tid; j < L1_N; j += 256) sT1[j] = g_T1[b * L1_N + j];
    for (int j = L1_N + tid; j < L1_PAD; j += 256) sT1[j] = 0.0f;
    __syncthreads();

    if (tid < L2_N) {
        float acc = 0.0f;
        int base = tid * 16;
        #pragma unroll
        for (int k = 0; k < 16; k++) {
            acc = __fadd_rn(acc, sT1[base + k]);
            sT1[base + k] = acc;
        }
        sT2[tid] = acc;
    }
    if (tid >= L2_N && tid < L2_PAD) sT2[tid] = 0.0f;
    __syncthreads();

    if (tid < L3_N) {
        float acc = 0.0f;
        int base = tid * 16;
        #pragma unroll
        for (int k = 0; k < 16; k++) {
            acc = __fadd_rn(acc, sT2[base + k]);
            sT2[base + k] = acc;
        }
        sT3[tid] = acc;
    }
    __syncthreads();

    if (tid == 0) {
        float acc = 0.0f;
        #pragma unroll
        for (int i = 0; i < L3_N; i++) {
            acc = __fadd_rn(acc, sT3[i]);
            sT3[i] = acc;
        }
    }
    __syncthreads();

    if (tid < L2_N) {
        int j3 = tid >> 4;
        sS2[tid] = j3 ? __fadd_rn(sT2[tid], sT3[j3 - 1]) : sT2[tid];
    }
    __syncthreads();

    for (int j = tid; j < L1_N; j += 256) {
        int j2 = j >> 4;
        g_S1[b * L1_N + j] = j2 ? __fadd_rn(sT1[j], sS2[j2 - 1]) : sT1[j];
    }

    if (tid == 0) {
        float s1v = __fadd_rn(sT1[2998], sS2[186]);
        float s0  = __fadd_rn(g_inner0[b][T_LEN - 1], s1v);
        float ph  = __fadd_rn(s0, initial_phase[b]);
        out[B_N * T_LEN + b] = fmodf(ph, TWOPI_F);
    }
}

// ---------------------------------------------------------------------------
// Kernel C: oscillator, occupancy-first: 256 thr, reg-capped via
// __launch_bounds__(256,4), rolled pair loop, global u64 amp loads.
// ---------------------------------------------------------------------------
struct PairCtx {
    u64 nfreq2[NFORM], bw22[NFORM], num2[NFORM];
    u64 F0S_2, PH_2, I2PI2, NC1_2, C2_2, MAG2, NMAG2, ONE2;
};

__device__ __forceinline__ u64 pair_term(const PairCtx& c, u64 hf2, u64 am2)
{
    u64 hfs2 = mul2(c.F0S_2, hf2);        // == 2^-10 * fl(f0*h) exactly
    u64 Np2 = am2, Dp2 = c.ONE2;
    #pragma unroll
    for (int f = 0; f < NFORM; f++) {
        u64 d2   = add2(hfs2, c.nfreq2[f]);
        u64 den2 = fma2(d2, d2, c.bw22[f]);
        u64 nd2  = add2(den2, c.num2[f]);
        Np2 = mul2(Np2, nd2);
        Dp2 = mul2(Dp2, den2);
    }

    u64 arg2 = mul2(c.PH_2, hf2);         // EXACT fl(phase*h) per lane
    u64 km2  = fma2(arg2, c.I2PI2, c.MAG2);
    u64 kq2  = add2(km2, c.NMAG2);
    u64 r2   = fma2(kq2, c.NC1_2, arg2);
    r2       = fma2(kq2, c.C2_2, r2);
    float r0, r1;
    unpk2(r2, r0, r1);
    u64 sv2 = pk2(__sinf(r0), __sinf(r1));

    float Dp0, Dp1;
    unpk2(Dp2, Dp0, Dp1);
    float inv = __fdividef(1.0f, __fmul_rn(Dp0, Dp1));
    u64 fact2 = mul2(mul2(Np2, pk2(Dp1, Dp0)), pk2(inv, inv));

    return mul2(sv2, fact2);
}

__global__ void __launch_bounds__(256, 4)
osc_kernel(const float* __restrict__ f0,
           const float* __restrict__ amplitudes,
           const float* __restrict__ formant_freqs,
           const float* __restrict__ formant_bws,
           const float* __restrict__ formant_amps,
           const float* __restrict__ initial_phase,
           float* __restrict__ out)
{
    int idx = blockIdx.x * blockDim.x + threadIdx.x;
    if (idx >= B_N * T_LEN) return;
    int b = idx / T_LEN;
    int t = idx - b * T_LEN;

    float f0v = f0[idx];

    // Compose phase: fl( fl(inner0[t] + S1[t/16 - 1]) + ip )
    int jt = t >> 4;
    float s0 = g_inner0[b][t];
    if (jt) s0 = __fadd_rn(s0, g_S1[b * L1_N + jt - 1]);
    float phase = __fadd_rn(s0, initial_phase[b]);

    // Exact harmonic count: nh = max{h : fl(f0*h) < 12000}
    int nh = min(MAX_H, (int)__fdividef(12000.0f, f0v));
    while (nh > 0 && !(__fmul_rn(f0v, (float)nh) < 12000.0f)) nh--;
    while (nh < MAX_H && __fmul_rn(f0v, (float)(nh + 1)) < 12000.0f) nh++;
    int npairs = (nh + 1) >> 1;

    // Linear interp of formant params (align_corners=True), exact f32 replica.
    const float SRC_SCALE = (float)(99.0 / 47999.0);
    float src = __fmul_rn((float)t, SRC_SCALE);
    int i0 = (int)floorf(src);
    i0 = max(0, min(C_N - 2, i0));
    float frac = __fsub_rn(src, (float)i0);
    float w0   = __fsub_rn(1.0f, frac);

    const float* fq = formant_freqs + (b * C_N + i0) * NFORM;
    const float* fb = formant_bws   + (b * C_N + i0) * NFORM;
    const float* fa = formant_amps  + (b * C_N + i0) * NFORM;

    PairCtx c;
    #pragma unroll
    for (int f = 0; f < NFORM; f++) {
        float fr = __fadd_rn(__fmul_rn(fq[f], w0), __fmul_rn(fq[f + NFORM], frac));
        float bw = __fadd_rn(__fmul_rn(fb[f], w0), __fmul_rn(fb[f + NFORM], frac));
        float am = __fadd_rn(__fmul_rn(fa[f], w0), __fmul_rn(fa[f + NFORM], frac));
        float bw2 = __fmul_rn(bw, bw);
        float num = __fmul_rn(__fmul_rn(am, bw), bw);
        float nfs = -__fmul_rn(fr,  SC1);
        float b2s = __fmul_rn(bw2, SC2);
        float nms = __fmul_rn(num, SC2);
        c.nfreq2[f] = pk2(nfs, nfs);
        c.bw22[f]   = pk2(b2s, b2s);
        c.num2[f]   = pk2(nms, nms);
    }
    float f0s = __fmul_rn(f0v, SC1);     // exact 2^-10 scale
    c.F0S_2 = pk2(f0s, f0s);
    c.PH_2  = pk2(phase, phase);
    c.I2PI2 = pk2(INV2PI_F, INV2PI_F);
    c.NC1_2 = pk2(-TWOPI_F, -TWOPI_F);
    c.C2_2  = pk2(C2_ABS, C2_ABS);
    c.MAG2  = pk2(RMAGIC, RMAGIC);
    c.NMAG2 = pk2(-RMAGIC, -RMAGIC);
    c.ONE2  = pk2(1.0f, 1.0f);

    const u64* arow2 =
        reinterpret_cast<const u64*>(amplitudes + (size_t)idx * MAX_H);

    u64 acc2 = pk2(0.0f, 0.0f);
    u64 hf2  = pk2(1.0f, 2.0f);
    const u64 TWO2 = pk2(2.0f, 2.0f);

    #pragma unroll 2
    for (int pi = 0; pi < npairs - 1; pi++) {
        acc2 = add2(acc2, pair_term(c, hf2, arow2[pi]));
        hf2  = add2(hf2, TWO2);
    }

    // Peeled last pair: mask hi lane if nh is odd.
    {
        u64 am2 = arow2[npairs - 1];
        if (nh & 1) am2 &= 0x00000000FFFFFFFFull;
        acc2 = add2(acc2, pair_term(c, hf2, am2));
    }

    float accLo, accHi;
    unpk2(acc2, accLo, accHi);
    float acc = __fadd_rn(accLo, accHi);

    float voiced = (f0v > 0.0f) ? 1.0f : 0.0f;
    out[idx] = __fmul_rn(acc, voiced);
}

// ---------------------------------------------------------------------------
extern "C" void kernel_launch(void* const* d_in, const int* in_sizes, int n_in,
                              void* d_out, int out_size)
{
    const float* f0   = (const float*)d_in[0];
    const float* amps = (const float*)d_in[1];
    const float* ffq  = (const float*)d_in[2];
    const float* fbw  = (const float*)d_in[3];
    const float* fam  = (const float*)d_in[4];
    const float* ip   = (const float*)d_in[5];
    float* out = (float*)d_out;

    int tiles = B_N * L1_N;
    scan_tiles_kernel<<<(tiles + 127) / 128, 128>>>(f0);
    scan_upper_kernel<<<B_N, 256>>>(ip, out);

    int total = B_N * T_LEN;
    osc_kernel<<<(total + 255) / 256, 256>>>(f0, amps, ffq, fbw, fam, ip, out);
}